// round 16
// baseline (speedup 1.0000x reference)
#include <cuda_runtime.h>
#include <cuda_bf16.h>
#include <cstdint>

#define BB 8
#define SS 1024
#define DD 1024
#define HH 16
#define DH 64
#define KDIM 1024

// ---------------- scratch (__device__ globals; allocation-free rule) --------
__device__ __nv_bfloat16 g_qkvh[(size_t)8192 * 3072]; // qkv hi
__device__ __nv_bfloat16 g_qkvl[(size_t)8192 * 3072]; // qkv lo
__device__ __nv_bfloat16 g_wqkv_h[3072 * 1024];       // W_qkv^T hi [N][K]
__device__ __nv_bfloat16 g_wqkv_l[3072 * 1024];
__device__ __nv_bfloat16 g_wout_h[1024 * 1024];       // W_out^T hi
__device__ __nv_bfloat16 g_wout_l[1024 * 1024];
__device__ __nv_bfloat16 g_ah[(size_t)8192 * 1024];   // activation / attn-out hi
__device__ __nv_bfloat16 g_al[(size_t)8192 * 1024];   // activation / attn-out lo

// ---------------- helpers ---------------------------------------------------
__device__ __forceinline__ uint32_t smem_u32(const void* p) {
    uint32_t a;
    asm("{ .reg .u64 t; cvta.to.shared.u64 t, %1; cvt.u32.u64 %0, t; }"
        : "=r"(a) : "l"(p));
    return a;
}
#define LDSM_X4(r, addr)                                                        \
    asm volatile("ldmatrix.sync.aligned.m8n8.x4.shared.b16 {%0,%1,%2,%3}, [%4];"\
        : "=r"((r)[0]), "=r"((r)[1]), "=r"((r)[2]), "=r"((r)[3]) : "r"(addr))
#define LDSM_X4_T(r, addr)                                                      \
    asm volatile("ldmatrix.sync.aligned.m8n8.x4.trans.shared.b16 {%0,%1,%2,%3}, [%4];"\
        : "=r"((r)[0]), "=r"((r)[1]), "=r"((r)[2]), "=r"((r)[3]) : "r"(addr))
// non-volatile in GEMM path
#define MMA16816(d, a, b0, b1)                                                  \
    asm("mma.sync.aligned.m16n8k16.row.col.f32.bf16.bf16.f32 "                  \
        "{%0,%1,%2,%3}, {%4,%5,%6,%7}, {%8,%9}, {%0,%1,%2,%3};"                 \
        : "+f"((d)[0]), "+f"((d)[1]), "+f"((d)[2]), "+f"((d)[3])                \
        : "r"((a)[0]), "r"((a)[1]), "r"((a)[2]), "r"((a)[3]), "r"(b0), "r"(b1))
// volatile variant (attention, proven)
#define MMA16816V(d, a, b0, b1)                                                 \
    asm volatile("mma.sync.aligned.m16n8k16.row.col.f32.bf16.bf16.f32 "         \
        "{%0,%1,%2,%3}, {%4,%5,%6,%7}, {%8,%9}, {%0,%1,%2,%3};"                 \
        : "+f"((d)[0]), "+f"((d)[1]), "+f"((d)[2]), "+f"((d)[3])                \
        : "r"((a)[0]), "r"((a)[1]), "r"((a)[2]), "r"((a)[3]), "r"(b0), "r"(b1))
#define CP_ASYNC16(sa, gp)                                                      \
    asm volatile("cp.async.cg.shared.global [%0], [%1], 16;"                    \
                 :: "r"(sa), "l"(gp) : "memory")
#define CP_COMMIT() asm volatile("cp.async.commit_group;" ::: "memory")
#define CP_WAIT0()  asm volatile("cp.async.wait_group 0;" ::: "memory")
#define CP_WAIT1()  asm volatile("cp.async.wait_group 1;" ::: "memory")
#define CP_WAIT2()  asm volatile("cp.async.wait_group 2;" ::: "memory")

__device__ __forceinline__ uint32_t pack_bf16(__nv_bfloat16 a, __nv_bfloat16 b) {
    return (uint32_t)__bfloat16_as_ushort(a) | ((uint32_t)__bfloat16_as_ushort(b) << 16);
}
__device__ __forceinline__ void split1(float v, __nv_bfloat16& h, __nv_bfloat16& l) {
    h = __float2bfloat16(v);
    float hf = __uint_as_float(((uint32_t)__bfloat16_as_ushort(h)) << 16);
    l = __float2bfloat16(v - hf);
}
__device__ __forceinline__ void split2(float a, float b, uint32_t& h, uint32_t& l) {
    __nv_bfloat16 ha, la, hb, lb;
    split1(a, ha, la); split1(b, hb, lb);
    h = pack_bf16(ha, hb); l = pack_bf16(la, lb);
}
__device__ __forceinline__ float ex2(float x) {
    float r;
    asm("ex2.approx.f32 %0, %1;" : "=f"(r) : "f"(x));
    return r;
}

// ---------------------------------------------------------------------------
// Weight pre-pass: W[K,N] fp32 -> H,L [N,K] bf16 (transpose + hi/lo split)
// ---------------------------------------------------------------------------
__global__ void __launch_bounds__(256)
wsplit_kernel(const float* __restrict__ W, __nv_bfloat16* __restrict__ H,
              __nv_bfloat16* __restrict__ L, int K, int N) {
    __shared__ float t[32][33];
    const int tx = threadIdx.x, ty = threadIdx.y;
    const int n0 = blockIdx.x * 32, k0 = blockIdx.y * 32;
#pragma unroll
    for (int i = 0; i < 32; i += 8)
        t[ty + i][tx] = W[(size_t)(k0 + ty + i) * N + n0 + tx];
    __syncthreads();
#pragma unroll
    for (int i = 0; i < 32; i += 8) {
        const int n = ty + i;
        float v = t[tx][n];
        __nv_bfloat16 h, l;
        split1(v, h, l);
        H[(size_t)(n0 + n) * K + k0 + tx] = h;
        L[(size_t)(n0 + n) * K + k0 + tx] = l;
    }
}

// ---------------------------------------------------------------------------
// Activation split: X fp32 [M][K] -> H,L bf16 same layout (elementwise)
// ---------------------------------------------------------------------------
__global__ void __launch_bounds__(256)
xsplit_kernel(const float* __restrict__ X, __nv_bfloat16* __restrict__ H,
              __nv_bfloat16* __restrict__ L) {
    const size_t i4 = (size_t)blockIdx.x * 256 + threadIdx.x;
    float4 v = *(const float4*)(X + i4 * 4);
    __nv_bfloat16 h0, h1, h2, h3, l0, l1, l2, l3;
    split1(v.x, h0, l0); split1(v.y, h1, l1);
    split1(v.z, h2, l2); split1(v.w, h3, l3);
    *(uint2*)(H + i4 * 4) = make_uint2(pack_bf16(h0, h1), pack_bf16(h2, h3));
    *(uint2*)(L + i4 * 4) = make_uint2(pack_bf16(l0, l1), pack_bf16(l2, l3));
}

// ---------------------------------------------------------------------------
// HMMA GEMM (bf16 3-term). BN-templated, optional split-K (ATOMIC epilogue).
// 256 threads, 8 warps (2x4), warp tile 64 x (BN/4), KC=64, 2-stage pipeline.
// B loaded per nt-PAIR via ldmatrix.x4; MMAs term-major within pair.
// ---------------------------------------------------------------------------
#define KC 64
#define RSTRIDE 144

template <int BN, int CHUNKS, bool SPLITOUT, bool ATOMIC>
__global__ void __launch_bounds__(256, 1)
gemm_mma(const __nv_bfloat16* __restrict__ Ah, const __nv_bfloat16* __restrict__ Al,
         const __nv_bfloat16* __restrict__ Wh, const __nv_bfloat16* __restrict__ Wl,
         float* __restrict__ C, __nv_bfloat16* __restrict__ Ch,
         __nv_bfloat16* __restrict__ Cl, int N) {
    constexpr int ABYTES = 128 * RSTRIDE;
    constexpr int BBYTES = BN * RSTRIDE;
    constexpr int OFF_AL = ABYTES;
    constexpr int OFF_BH = 2 * ABYTES;
    constexpr int STAGE = 2 * ABYTES + 2 * BBYTES;
    constexpr int NT = BN / 32;
    constexpr int NP = NT / 2;

    extern __shared__ char smem[];
    const uint32_t sb = smem_u32(smem);
    const int tid = threadIdx.x;
    const int warp = tid >> 5, lane = tid & 31;
    const int m0 = blockIdx.y * 128, n0 = blockIdx.x * BN;
    const int kbase0 = blockIdx.z * CHUNKS;        // split-K offset (chunks)
    const int wm = (warp >> 2) * 64;
    const int wn = (warp & 3) * (BN / 4);

    float acc[4][NT][4];
#pragma unroll
    for (int mt = 0; mt < 4; mt++)
#pragma unroll
        for (int nt = 0; nt < NT; nt++)
#pragma unroll
            for (int i = 0; i < 4; i++) acc[mt][nt][i] = 0.f;

    auto issue_stage = [&](int s) {
        const uint32_t so = sb + (uint32_t)(s & 1) * STAGE;
        const int k0 = (kbase0 + s) * KC;
#pragma unroll
        for (int i = 0; i < 4; i++) {
            const int idx = tid + i * 256;
            const int row = idx >> 3;
            const int k8 = (idx & 7) * 8;
            const uint32_t soff = so + (uint32_t)row * RSTRIDE + (uint32_t)k8 * 2;
            const size_t ga = (size_t)(m0 + row) * KDIM + k0 + k8;
            CP_ASYNC16(soff,          Ah + ga);
            CP_ASYNC16(soff + OFF_AL, Al + ga);
        }
#pragma unroll
        for (int i = 0; i < BN / 32; i++) {
            const int idx = tid + i * 256;
            const int row = idx >> 3;
            const int k8 = (idx & 7) * 8;
            const uint32_t soff = so + OFF_BH + (uint32_t)row * RSTRIDE + (uint32_t)k8 * 2;
            const size_t gb = (size_t)(n0 + row) * KDIM + k0 + k8;
            CP_ASYNC16(soff, Wh + gb);
            CP_ASYNC16(soff + BBYTES, Wl + gb);
        }
    };

    issue_stage(0); CP_COMMIT();
    issue_stage(1); CP_COMMIT();

#pragma unroll 1
    for (int c = 0; c < CHUNKS; c++) {
        if (c == CHUNKS - 1) { CP_WAIT0(); } else { CP_WAIT1(); }
        __syncthreads();

        const uint32_t cur = (uint32_t)(c & 1) * STAGE;
        const uint32_t abase = sb + cur + (uint32_t)(wm + (lane & 15)) * RSTRIDE
                             + (uint32_t)(lane >> 4) * 16;
        const uint32_t bpbase = sb + cur + OFF_BH
                              + (uint32_t)(wn + ((lane >> 4) & 1) * 8 + (lane & 7)) * RSTRIDE
                              + (uint32_t)((lane >> 3) & 1) * 16;
#pragma unroll
        for (int k16 = 0; k16 < 4; k16++) {
            uint32_t ah4[4][4], al4[4][4];
#pragma unroll
            for (int mt = 0; mt < 4; mt++) {
                const uint32_t aa = abase + mt * 16 * RSTRIDE + k16 * 32;
                LDSM_X4(ah4[mt], aa);
                LDSM_X4(al4[mt], aa + OFF_AL);
            }
#pragma unroll
            for (int p = 0; p < NP; p++) {
                uint32_t bh[4], bl[4];
                const uint32_t ba = bpbase + p * 16 * RSTRIDE + k16 * 32;
                LDSM_X4(bh, ba);
                LDSM_X4(bl, ba + BBYTES);
                const int n0t = 2 * p, n1t = 2 * p + 1;
#pragma unroll
                for (int mt = 0; mt < 4; mt++) MMA16816(acc[mt][n0t], ah4[mt], bh[0], bh[1]);
#pragma unroll
                for (int mt = 0; mt < 4; mt++) MMA16816(acc[mt][n1t], ah4[mt], bh[2], bh[3]);
#pragma unroll
                for (int mt = 0; mt < 4; mt++) MMA16816(acc[mt][n0t], ah4[mt], bl[0], bl[1]);
#pragma unroll
                for (int mt = 0; mt < 4; mt++) MMA16816(acc[mt][n1t], ah4[mt], bl[2], bl[3]);
#pragma unroll
                for (int mt = 0; mt < 4; mt++) MMA16816(acc[mt][n0t], al4[mt], bh[0], bh[1]);
#pragma unroll
                for (int mt = 0; mt < 4; mt++) MMA16816(acc[mt][n1t], al4[mt], bh[2], bh[3]);
            }
        }
        __syncthreads();
        if (c + 2 < CHUNKS) { issue_stage(c + 2); CP_COMMIT(); }
    }

#pragma unroll
    for (int mt = 0; mt < 4; mt++) {
        const int row = m0 + wm + mt * 16 + (lane >> 2);
#pragma unroll
        for (int nt = 0; nt < NT; nt++) {
            const int col = n0 + wn + nt * 8 + (lane & 3) * 2;
            if (ATOMIC) {
                atomicAdd(C + (size_t)row * N + col,           acc[mt][nt][0]);
                atomicAdd(C + (size_t)row * N + col + 1,       acc[mt][nt][1]);
                atomicAdd(C + (size_t)(row + 8) * N + col,     acc[mt][nt][2]);
                atomicAdd(C + (size_t)(row + 8) * N + col + 1, acc[mt][nt][3]);
            } else if (SPLITOUT) {
                uint32_t h01, l01, h23, l23;
                split2(acc[mt][nt][0], acc[mt][nt][1], h01, l01);
                split2(acc[mt][nt][2], acc[mt][nt][3], h23, l23);
                *(uint32_t*)(Ch + (size_t)row * N + col) = h01;
                *(uint32_t*)(Cl + (size_t)row * N + col) = l01;
                *(uint32_t*)(Ch + (size_t)(row + 8) * N + col) = h23;
                *(uint32_t*)(Cl + (size_t)(row + 8) * N + col) = l23;
            } else {
                *(float2*)(C + (size_t)row * N + col) =
                    make_float2(acc[mt][nt][0], acc[mt][nt][1]);
                *(float2*)(C + (size_t)(row + 8) * N + col) =
                    make_float2(acc[mt][nt][2], acc[mt][nt][3]);
            }
        }
    }
}

#define GEMM_SMEM_192 (2 * (2 * 128 * RSTRIDE + 2 * 192 * RSTRIDE))
#define GEMM_SMEM_128 (2 * (2 * 128 * RSTRIDE + 2 * 128 * RSTRIDE))

// ---------------------------------------------------------------------------
// HMMA causal flash attention (R13/R15 proven version, volatile MMAs).
// ---------------------------------------------------------------------------
#define A_OFF_QH 0
#define A_OFF_QL 18432
#define A_KV0 36864
#define A_KVSTAGE 36864
#define ATT_SMEM (A_KV0 + 3 * A_KVSTAGE)

__global__ void __launch_bounds__(256, 1)
attn_mma(const __nv_bfloat16* __restrict__ qkvh, const __nv_bfloat16* __restrict__ qkvl,
         __nv_bfloat16* __restrict__ Oh, __nv_bfloat16* __restrict__ Ol) {
    extern __shared__ char smem[];
    const uint32_t sb = smem_u32(smem);
    const int tid = threadIdx.x;
    const int warp = tid >> 5, lane = tid & 31;
    const int qt = 7 - blockIdx.x;
    const int b = blockIdx.y >> 4, h = blockIdx.y & 15;
    const int qrow0 = qt * 128;
    const size_t rowbase = (size_t)b * SS;
    const int jlast = 2 * qt + 1;

#pragma unroll
    for (int i = 0; i < 4; i++) {
        const int idx = tid + i * 256;
        const int row = idx >> 3;
        const int c8 = (idx & 7) * 8;
        const size_t g = (rowbase + qrow0 + row) * 3072 + h * DH + c8;
        const uint32_t so = sb + (uint32_t)row * RSTRIDE + (uint32_t)c8 * 2;
        CP_ASYNC16(so + A_OFF_QH, qkvh + g);
        CP_ASYNC16(so + A_OFF_QL, qkvl + g);
    }
    auto issue_kv = [&](int j) {
        const uint32_t so = sb + A_KV0 + (uint32_t)(j % 3) * A_KVSTAGE;
#pragma unroll
        for (int i = 0; i < 2; i++) {
            const int idx = tid + i * 256;
            const int row = idx >> 3;
            const int c8 = (idx & 7) * 8;
            const size_t g = (rowbase + j * 64 + row) * 3072 + h * DH + c8;
            const uint32_t soff = so + (uint32_t)row * RSTRIDE + (uint32_t)c8 * 2;
            CP_ASYNC16(soff,         qkvh + g + 1024);
            CP_ASYNC16(soff + 9216,  qkvl + g + 1024);
            CP_ASYNC16(soff + 18432, qkvh + g + 2048);
            CP_ASYNC16(soff + 27648, qkvl + g + 2048);
        }
    };
    issue_kv(0); CP_COMMIT();
    if (jlast >= 1) { issue_kv(1); CP_COMMIT(); }

    if (jlast >= 1) { CP_WAIT1(); } else { CP_WAIT0(); }
    __syncthreads();

    uint32_t qh[4][4], ql[4][4];
    {
        const uint32_t qbase = sb + (uint32_t)(warp * 16 + (lane & 15)) * RSTRIDE
                             + (uint32_t)(lane >> 4) * 16;
#pragma unroll
        for (int ks = 0; ks < 4; ks++) {
            LDSM_X4(qh[ks], qbase + A_OFF_QH + ks * 32);
            LDSM_X4(ql[ks], qbase + A_OFF_QL + ks * 32);
        }
    }

    float O[8][4];
#pragma unroll
    for (int dt = 0; dt < 8; dt++)
#pragma unroll
        for (int i = 0; i < 4; i++) O[dt][i] = 0.f;
    float m0 = -1e30f, m1 = -1e30f, l0 = 0.f, l1 = 0.f;

    const int rg0 = qrow0 + warp * 16 + (lane >> 2);
    const float SC = 0.18033688011112042f;

#pragma unroll 1
    for (int j = 0; j <= jlast; j++) {
        if (j + 2 <= jlast) { issue_kv(j + 2); CP_COMMIT(); }
        if (j + 2 <= jlast)      { CP_WAIT2(); }
        else if (j + 1 <= jlast) { CP_WAIT1(); }
        else                     { CP_WAIT0(); }
        __syncthreads();

        const bool active = (64 * j) <= (qrow0 + warp * 16 + 15);
        if (active) {
            const uint32_t so = sb + A_KV0 + (uint32_t)(j % 3) * A_KVSTAGE;

            float S[8][4];
#pragma unroll
            for (int nt = 0; nt < 8; nt++)
#pragma unroll
                for (int i = 0; i < 4; i++) S[nt][i] = 0.f;

            const uint32_t kbase = so + (uint32_t)(lane & 7) * RSTRIDE
                                 + (uint32_t)(lane >> 3) * 16;
#pragma unroll
            for (int nt = 0; nt < 8; nt++) {
                const uint32_t ka = kbase + nt * 8 * RSTRIDE;
                uint32_t kh0[4], kh1[4], kl0[4], kl1[4];
                LDSM_X4(kh0, ka);          LDSM_X4(kh1, ka + 64);
                LDSM_X4(kl0, ka + 9216);   LDSM_X4(kl1, ka + 9216 + 64);
                MMA16816V(S[nt], qh[0], kh0[0], kh0[1]);
                MMA16816V(S[nt], qh[1], kh0[2], kh0[3]);
                MMA16816V(S[nt], qh[2], kh1[0], kh1[1]);
                MMA16816V(S[nt], qh[3], kh1[2], kh1[3]);
                MMA16816V(S[nt], qh[0], kl0[0], kl0[1]);
                MMA16816V(S[nt], qh[1], kl0[2], kl0[3]);
                MMA16816V(S[nt], qh[2], kl1[0], kl1[1]);
                MMA16816V(S[nt], qh[3], kl1[2], kl1[3]);
                MMA16816V(S[nt], ql[0], kh0[0], kh0[1]);
                MMA16816V(S[nt], ql[1], kh0[2], kh0[3]);
                MMA16816V(S[nt], ql[2], kh1[0], kh1[1]);
                MMA16816V(S[nt], ql[3], kh1[2], kh1[3]);
            }

            const bool needmask = (j >= 2 * qt);
            float mx0 = -1e30f, mx1 = -1e30f;
#pragma unroll
            for (int nt = 0; nt < 8; nt++) {
                float t0 = S[nt][0] * SC, t1 = S[nt][1] * SC;
                float t2 = S[nt][2] * SC, t3 = S[nt][3] * SC;
                if (needmask) {
                    const int col = 64 * j + 8 * nt + 2 * (lane & 3);
                    if (col > rg0)         t0 = -1e30f;
                    if (col + 1 > rg0)     t1 = -1e30f;
                    if (col > rg0 + 8)     t2 = -1e30f;
                    if (col + 1 > rg0 + 8) t3 = -1e30f;
                }
                S[nt][0] = t0; S[nt][1] = t1; S[nt][2] = t2; S[nt][3] = t3;
                mx0 = fmaxf(mx0, fmaxf(t0, t1));
                mx1 = fmaxf(mx1, fmaxf(t2, t3));
            }
            mx0 = fmaxf(mx0, __shfl_xor_sync(0xffffffffu, mx0, 1));
            mx0 = fmaxf(mx0, __shfl_xor_sync(0xffffffffu, mx0, 2));
            mx1 = fmaxf(mx1, __shfl_xor_sync(0xffffffffu, mx1, 1));
            mx1 = fmaxf(mx1, __shfl_xor_sync(0xffffffffu, mx1, 2));

            const float mn0 = fmaxf(m0, mx0), mn1 = fmaxf(m1, mx1);
            const float cr0 = ex2(m0 - mn0), cr1 = ex2(m1 - mn1);
            m0 = mn0; m1 = mn1;

            float ls0 = 0.f, ls1 = 0.f;
#pragma unroll
            for (int nt = 0; nt < 8; nt++) {
                const float p0 = ex2(S[nt][0] - m0), p1 = ex2(S[nt][1] - m0);
                const float p2 = ex2(S[nt][2] - m1), p3 = ex2(S[nt][3] - m1);
                S[nt][0] = p0; S[nt][1] = p1; S[nt][2] = p2; S[nt][3] = p3;
                ls0 += p0 + p1;
                ls1 += p2 + p3;
            }
            ls0 += __shfl_xor_sync(0xffffffffu, ls0, 1);
            ls0 += __shfl_xor_sync(0xffffffffu, ls0, 2);
            ls1 += __shfl_xor_sync(0xffffffffu, ls1, 1);
            ls1 += __shfl_xor_sync(0xffffffffu, ls1, 2);
            l0 = l0 * cr0 + ls0;
            l1 = l1 * cr1 + ls1;

#pragma unroll
            for (int dt = 0; dt < 8; dt++) {
                O[dt][0] *= cr0; O[dt][1] *= cr0;
                O[dt][2] *= cr1; O[dt][3] *= cr1;
            }

            uint32_t ph[4][4], pl[4][4];
#pragma unroll
            for (int ks = 0; ks < 4; ks++) {
                split2(S[2 * ks][0],     S[2 * ks][1],     ph[ks][0], pl[ks][0]);
                split2(S[2 * ks][2],     S[2 * ks][3],     ph[ks][1], pl[ks][1]);
                split2(S[2 * ks + 1][0], S[2 * ks + 1][1], ph[ks][2], pl[ks][2]);
                split2(S[2 * ks + 1][2], S[2 * ks + 1][3], ph[ks][3], pl[ks][3]);
            }

            const uint32_t vbase = so + 18432 + (uint32_t)lane * RSTRIDE;
#pragma unroll
            for (int dt = 0; dt < 8; dt++) {
                const uint32_t va = vbase + dt * 16;
                uint32_t vh0[4], vh1[4], vl0[4], vl1[4];
                LDSM_X4_T(vh0, va);                 LDSM_X4_T(vh1, va + 32 * RSTRIDE);
                LDSM_X4_T(vl0, va + 9216);          LDSM_X4_T(vl1, va + 9216 + 32 * RSTRIDE);
                MMA16816V(O[dt], ph[0], vh0[0], vh0[1]);
                MMA16816V(O[dt], ph[1], vh0[2], vh0[3]);
                MMA16816V(O[dt], ph[2], vh1[0], vh1[1]);
                MMA16816V(O[dt], ph[3], vh1[2], vh1[3]);
                MMA16816V(O[dt], ph[0], vl0[0], vl0[1]);
                MMA16816V(O[dt], ph[1], vl0[2], vl0[3]);
                MMA16816V(O[dt], ph[2], vl1[0], vl1[1]);
                MMA16816V(O[dt], ph[3], vl1[2], vl1[3]);
                MMA16816V(O[dt], pl[0], vh0[0], vh0[1]);
                MMA16816V(O[dt], pl[1], vh0[2], vh0[3]);
                MMA16816V(O[dt], pl[2], vh1[0], vh1[1]);
                MMA16816V(O[dt], pl[3], vh1[2], vh1[3]);
            }
        }
        __syncthreads();
    }

    const float inv0 = 1.f / l0, inv1 = 1.f / l1;
    const size_t row0 = rowbase + qrow0 + warp * 16 + (lane >> 2);
    const size_t row1 = row0 + 8;
#pragma unroll
    for (int dt = 0; dt < 8; dt++) {
        const int col = h * DH + dt * 8 + 2 * (lane & 3);
        uint32_t h01, l01, h23, l23;
        split2(O[dt][0] * inv0, O[dt][1] * inv0, h01, l01);
        split2(O[dt][2] * inv1, O[dt][3] * inv1, h23, l23);
        *(uint32_t*)(Oh + row0 * DD + col) = h01;
        *(uint32_t*)(Ol + row0 * DD + col) = l01;
        *(uint32_t*)(Oh + row1 * DD + col) = h23;
        *(uint32_t*)(Ol + row1 * DD + col) = l23;
    }
}

// ---------------------------------------------------------------------------
extern "C" void kernel_launch(void* const* d_in, const int* in_sizes, int n_in,
                              void* d_out, int out_size) {
    const float* x     = (const float*)d_in[0];
    const float* w_qkv = (const float*)d_in[2];
    const float* w_out = (const float*)d_in[3];
    float* out = (float*)d_out;

    __nv_bfloat16 *wqh, *wql, *woh, *wol, *ah, *al, *qkvh, *qkvl;
    cudaGetSymbolAddress((void**)&wqh, g_wqkv_h);
    cudaGetSymbolAddress((void**)&wql, g_wqkv_l);
    cudaGetSymbolAddress((void**)&woh, g_wout_h);
    cudaGetSymbolAddress((void**)&wol, g_wout_l);
    cudaGetSymbolAddress((void**)&ah, g_ah);
    cudaGetSymbolAddress((void**)&al, g_al);
    cudaGetSymbolAddress((void**)&qkvh, g_qkvh);
    cudaGetSymbolAddress((void**)&qkvl, g_qkvl);

    cudaFuncSetAttribute((const void*)gemm_mma<192, 16, true, false>,
                         cudaFuncAttributeMaxDynamicSharedMemorySize, GEMM_SMEM_192);
    cudaFuncSetAttribute((const void*)gemm_mma<128, 8, false, true>,
                         cudaFuncAttributeMaxDynamicSharedMemorySize, GEMM_SMEM_128);
    cudaFuncSetAttribute(attn_mma, cudaFuncAttributeMaxDynamicSharedMemorySize, ATT_SMEM);

    // 0) weight transpose+split, activation split; zero output for atomics
    wsplit_kernel<<<dim3(3072 / 32, 1024 / 32), dim3(32, 8)>>>(w_qkv, wqh, wql, 1024, 3072);
    wsplit_kernel<<<dim3(1024 / 32, 1024 / 32), dim3(32, 8)>>>(w_out, woh, wol, 1024, 1024);
    xsplit_kernel<<<(8192 * 1024 / 4) / 256, 256>>>(x, ah, al);
    cudaMemsetAsync(out, 0, (size_t)8192 * 1024 * sizeof(float));

    // 1) QKV projection: 128x192 tiles -> 1024 CTAs (~1% wave tail)
    gemm_mma<192, 16, true, false><<<dim3(3072 / 192, 8192 / 128), 256, GEMM_SMEM_192>>>(
        ah, al, wqh, wql, nullptr, qkvh, qkvl, 3072);

    // 2) causal flash attention (HMMA) -> split bf16 O
    attn_mma<<<dim3(8, BB * HH), 256, ATT_SMEM>>>(qkvh, qkvl, ah, al);

    // 3) output projection: split-K=2, 128x128 tiles -> 1024 CTAs (~1% tail),
    //    2 deterministic (commutative) fp32 atomicAdd contributions per element
    gemm_mma<128, 8, false, true><<<dim3(1024 / 128, 8192 / 128, 2), 256, GEMM_SMEM_128>>>(
        ah, al, woh, wol, out, nullptr, nullptr, 1024);
}

// round 17
// speedup vs baseline: 1.5824x; 1.5824x over previous
#include <cuda_runtime.h>
#include <cuda_bf16.h>
#include <cstdint>

#define BB 8
#define SS 1024
#define DD 1024
#define HH 16
#define DH 64
#define KDIM 1024

// ---------------- scratch (__device__ globals; allocation-free rule) --------
__device__ __nv_bfloat16 g_qkvh[(size_t)8192 * 3072]; // qkv hi
__device__ __nv_bfloat16 g_qkvl[(size_t)8192 * 3072]; // qkv lo
__device__ __nv_bfloat16 g_wqkv_h[3072 * 1024];       // W_qkv^T hi [N][K]
__device__ __nv_bfloat16 g_wqkv_l[3072 * 1024];
__device__ __nv_bfloat16 g_wout_h[1024 * 1024];       // W_out^T hi
__device__ __nv_bfloat16 g_wout_l[1024 * 1024];
__device__ __nv_bfloat16 g_ah[(size_t)8192 * 1024];   // activation / attn-out hi
__device__ __nv_bfloat16 g_al[(size_t)8192 * 1024];   // activation / attn-out lo

// ---------------- helpers ---------------------------------------------------
__device__ __forceinline__ uint32_t smem_u32(const void* p) {
    uint32_t a;
    asm("{ .reg .u64 t; cvta.to.shared.u64 t, %1; cvt.u32.u64 %0, t; }"
        : "=r"(a) : "l"(p));
    return a;
}
#define LDSM_X4(r, addr)                                                        \
    asm volatile("ldmatrix.sync.aligned.m8n8.x4.shared.b16 {%0,%1,%2,%3}, [%4];"\
        : "=r"((r)[0]), "=r"((r)[1]), "=r"((r)[2]), "=r"((r)[3]) : "r"(addr))
#define LDSM_X4_T(r, addr)                                                      \
    asm volatile("ldmatrix.sync.aligned.m8n8.x4.trans.shared.b16 {%0,%1,%2,%3}, [%4];"\
        : "=r"((r)[0]), "=r"((r)[1]), "=r"((r)[2]), "=r"((r)[3]) : "r"(addr))
// non-volatile in GEMM path: ptxas may reorder/interleave independent chains
#define MMA16816(d, a, b0, b1)                                                  \
    asm("mma.sync.aligned.m16n8k16.row.col.f32.bf16.bf16.f32 "                  \
        "{%0,%1,%2,%3}, {%4,%5,%6,%7}, {%8,%9}, {%0,%1,%2,%3};"                 \
        : "+f"((d)[0]), "+f"((d)[1]), "+f"((d)[2]), "+f"((d)[3])                \
        : "r"((a)[0]), "r"((a)[1]), "r"((a)[2]), "r"((a)[3]), "r"(b0), "r"(b1))
// volatile variant for the attention kernel (proven behavior)
#define MMA16816V(d, a, b0, b1)                                                 \
    asm volatile("mma.sync.aligned.m16n8k16.row.col.f32.bf16.bf16.f32 "         \
        "{%0,%1,%2,%3}, {%4,%5,%6,%7}, {%8,%9}, {%0,%1,%2,%3};"                 \
        : "+f"((d)[0]), "+f"((d)[1]), "+f"((d)[2]), "+f"((d)[3])                \
        : "r"((a)[0]), "r"((a)[1]), "r"((a)[2]), "r"((a)[3]), "r"(b0), "r"(b1))
#define CP_ASYNC16(sa, gp)                                                      \
    asm volatile("cp.async.cg.shared.global [%0], [%1], 16;"                    \
                 :: "r"(sa), "l"(gp) : "memory")
#define CP_COMMIT() asm volatile("cp.async.commit_group;" ::: "memory")
#define CP_WAIT0()  asm volatile("cp.async.wait_group 0;" ::: "memory")
#define CP_WAIT1()  asm volatile("cp.async.wait_group 1;" ::: "memory")
#define CP_WAIT2()  asm volatile("cp.async.wait_group 2;" ::: "memory")

__device__ __forceinline__ uint32_t pack_bf16(__nv_bfloat16 a, __nv_bfloat16 b) {
    return (uint32_t)__bfloat16_as_ushort(a) | ((uint32_t)__bfloat16_as_ushort(b) << 16);
}
__device__ __forceinline__ void split1(float v, __nv_bfloat16& h, __nv_bfloat16& l) {
    h = __float2bfloat16(v);
    float hf = __uint_as_float(((uint32_t)__bfloat16_as_ushort(h)) << 16);
    l = __float2bfloat16(v - hf);
}
__device__ __forceinline__ void split2(float a, float b, uint32_t& h, uint32_t& l) {
    __nv_bfloat16 ha, la, hb, lb;
    split1(a, ha, la); split1(b, hb, lb);
    h = pack_bf16(ha, hb); l = pack_bf16(la, lb);
}
__device__ __forceinline__ float ex2(float x) {
    float r;
    asm("ex2.approx.f32 %0, %1;" : "=f"(r) : "f"(x));
    return r;
}

// ---------------------------------------------------------------------------
// Weight pre-pass: W[K,N] fp32 -> H,L [N,K] bf16 (transpose + hi/lo split)
// ---------------------------------------------------------------------------
__global__ void __launch_bounds__(256)
wsplit_kernel(const float* __restrict__ W, __nv_bfloat16* __restrict__ H,
              __nv_bfloat16* __restrict__ L, int K, int N) {
    __shared__ float t[32][33];
    const int tx = threadIdx.x, ty = threadIdx.y;
    const int n0 = blockIdx.x * 32, k0 = blockIdx.y * 32;
#pragma unroll
    for (int i = 0; i < 32; i += 8)
        t[ty + i][tx] = W[(size_t)(k0 + ty + i) * N + n0 + tx];
    __syncthreads();
#pragma unroll
    for (int i = 0; i < 32; i += 8) {
        const int n = ty + i;
        float v = t[tx][n];
        __nv_bfloat16 h, l;
        split1(v, h, l);
        H[(size_t)(n0 + n) * K + k0 + tx] = h;
        L[(size_t)(n0 + n) * K + k0 + tx] = l;
    }
}

// ---------------------------------------------------------------------------
// Activation split: X fp32 [M][K] -> H,L bf16 same layout (elementwise)
// ---------------------------------------------------------------------------
__global__ void __launch_bounds__(256)
xsplit_kernel(const float* __restrict__ X, __nv_bfloat16* __restrict__ H,
              __nv_bfloat16* __restrict__ L) {
    const size_t i4 = (size_t)blockIdx.x * 256 + threadIdx.x;
    float4 v = *(const float4*)(X + i4 * 4);
    __nv_bfloat16 h0, h1, h2, h3, l0, l1, l2, l3;
    split1(v.x, h0, l0); split1(v.y, h1, l1);
    split1(v.z, h2, l2); split1(v.w, h3, l3);
    *(uint2*)(H + i4 * 4) = make_uint2(pack_bf16(h0, h1), pack_bf16(h2, h3));
    *(uint2*)(L + i4 * 4) = make_uint2(pack_bf16(l0, l1), pack_bf16(l2, l3));
}

// ---------------------------------------------------------------------------
// HMMA GEMM (bf16 3-term), templated on CTA N-tile BN (192 or 256).
// 256 threads, 8 warps (2x4), warp tile 64 x (BN/4), KC=64, 2-stage pipeline.
// B loaded per nt-PAIR via ldmatrix.x4; MMAs term-major within pair.
// ---------------------------------------------------------------------------
#define KC 64
#define RSTRIDE 144
#define NCHUNK 16

template <int BN, bool SPLITOUT>
__global__ void __launch_bounds__(256, 1)
gemm_mma(const __nv_bfloat16* __restrict__ Ah, const __nv_bfloat16* __restrict__ Al,
         const __nv_bfloat16* __restrict__ Wh, const __nv_bfloat16* __restrict__ Wl,
         float* __restrict__ C, __nv_bfloat16* __restrict__ Ch,
         __nv_bfloat16* __restrict__ Cl, int N) {
    constexpr int ABYTES = 128 * RSTRIDE;
    constexpr int BBYTES = BN * RSTRIDE;
    constexpr int OFF_AL = ABYTES;
    constexpr int OFF_BH = 2 * ABYTES;
    constexpr int STAGE = 2 * ABYTES + 2 * BBYTES;
    constexpr int NT = BN / 32;                      // n-subtiles per warp (6/8)
    constexpr int NP = NT / 2;                       // nt pairs (3/4)

    extern __shared__ char smem[];
    const uint32_t sb = smem_u32(smem);
    const int tid = threadIdx.x;
    const int warp = tid >> 5, lane = tid & 31;
    const int m0 = blockIdx.y * 128, n0 = blockIdx.x * BN;
    const int wm = (warp >> 2) * 64;
    const int wn = (warp & 3) * (BN / 4);

    float acc[4][NT][4];
#pragma unroll
    for (int mt = 0; mt < 4; mt++)
#pragma unroll
        for (int nt = 0; nt < NT; nt++)
#pragma unroll
            for (int i = 0; i < 4; i++) acc[mt][nt][i] = 0.f;

    auto issue_stage = [&](int s) {
        const uint32_t so = sb + (uint32_t)(s & 1) * STAGE;
        const int k0 = s * KC;
#pragma unroll
        for (int i = 0; i < 4; i++) {
            const int idx = tid + i * 256;
            const int row = idx >> 3;
            const int k8 = (idx & 7) * 8;
            const uint32_t soff = so + (uint32_t)row * RSTRIDE + (uint32_t)k8 * 2;
            const size_t ga = (size_t)(m0 + row) * KDIM + k0 + k8;
            CP_ASYNC16(soff,          Ah + ga);
            CP_ASYNC16(soff + OFF_AL, Al + ga);
        }
#pragma unroll
        for (int i = 0; i < BN / 32; i++) {
            const int idx = tid + i * 256;
            const int row = idx >> 3;
            const int k8 = (idx & 7) * 8;
            const uint32_t soff = so + OFF_BH + (uint32_t)row * RSTRIDE + (uint32_t)k8 * 2;
            const size_t gb = (size_t)(n0 + row) * KDIM + k0 + k8;
            CP_ASYNC16(soff, Wh + gb);
            CP_ASYNC16(soff + BBYTES, Wl + gb);
        }
    };

    issue_stage(0); CP_COMMIT();
    issue_stage(1); CP_COMMIT();

#pragma unroll 1
    for (int c = 0; c < NCHUNK; c++) {
        if (c == NCHUNK - 1) { CP_WAIT0(); } else { CP_WAIT1(); }
        __syncthreads();

        const uint32_t cur = (uint32_t)(c & 1) * STAGE;
        const uint32_t abase = sb + cur + (uint32_t)(wm + (lane & 15)) * RSTRIDE
                             + (uint32_t)(lane >> 4) * 16;
        // B pair base: 4 ldmatrix address groups cover {nt, col0/col16, nt+1}
        const uint32_t bpbase = sb + cur + OFF_BH
                              + (uint32_t)(wn + ((lane >> 4) & 1) * 8 + (lane & 7)) * RSTRIDE
                              + (uint32_t)((lane >> 3) & 1) * 16;
#pragma unroll
        for (int k16 = 0; k16 < 4; k16++) {
            uint32_t ah4[4][4], al4[4][4];
#pragma unroll
            for (int mt = 0; mt < 4; mt++) {
                const uint32_t aa = abase + mt * 16 * RSTRIDE + k16 * 32;
                LDSM_X4(ah4[mt], aa);
                LDSM_X4(al4[mt], aa + OFF_AL);
            }
#pragma unroll
            for (int p = 0; p < NP; p++) {
                uint32_t bh[4], bl[4];
                const uint32_t ba = bpbase + p * 16 * RSTRIDE + k16 * 32;
                LDSM_X4(bh, ba);
                LDSM_X4(bl, ba + BBYTES);
                const int n0t = 2 * p, n1t = 2 * p + 1;
#pragma unroll
                for (int mt = 0; mt < 4; mt++) MMA16816(acc[mt][n0t], ah4[mt], bh[0], bh[1]);
#pragma unroll
                for (int mt = 0; mt < 4; mt++) MMA16816(acc[mt][n1t], ah4[mt], bh[2], bh[3]);
#pragma unroll
                for (int mt = 0; mt < 4; mt++) MMA16816(acc[mt][n0t], ah4[mt], bl[0], bl[1]);
#pragma unroll
                for (int mt = 0; mt < 4; mt++) MMA16816(acc[mt][n1t], ah4[mt], bl[2], bl[3]);
#pragma unroll
                for (int mt = 0; mt < 4; mt++) MMA16816(acc[mt][n0t], al4[mt], bh[0], bh[1]);
#pragma unroll
                for (int mt = 0; mt < 4; mt++) MMA16816(acc[mt][n1t], al4[mt], bh[2], bh[3]);
            }
        }
        __syncthreads();
        if (c + 2 < NCHUNK) { issue_stage(c + 2); CP_COMMIT(); }
    }

#pragma unroll
    for (int mt = 0; mt < 4; mt++) {
        const int row = m0 + wm + mt * 16 + (lane >> 2);
#pragma unroll
        for (int nt = 0; nt < NT; nt++) {
            const int col = n0 + wn + nt * 8 + (lane & 3) * 2;
            if (SPLITOUT) {
                uint32_t h01, l01, h23, l23;
                split2(acc[mt][nt][0], acc[mt][nt][1], h01, l01);
                split2(acc[mt][nt][2], acc[mt][nt][3], h23, l23);
                *(uint32_t*)(Ch + (size_t)row * N + col) = h01;
                *(uint32_t*)(Cl + (size_t)row * N + col) = l01;
                *(uint32_t*)(Ch + (size_t)(row + 8) * N + col) = h23;
                *(uint32_t*)(Cl + (size_t)(row + 8) * N + col) = l23;
            } else {
                *(float2*)(C + (size_t)row * N + col) =
                    make_float2(acc[mt][nt][0], acc[mt][nt][1]);
                *(float2*)(C + (size_t)(row + 8) * N + col) =
                    make_float2(acc[mt][nt][2], acc[mt][nt][3]);
            }
        }
    }
}

#define GEMM_SMEM_192 (2 * (2 * 128 * RSTRIDE + 2 * 192 * RSTRIDE))
#define GEMM_SMEM_256 (2 * (2 * 128 * RSTRIDE + 2 * 256 * RSTRIDE))

// ---------------------------------------------------------------------------
// HMMA causal flash attention (proven version, volatile MMAs).
// ---------------------------------------------------------------------------
#define A_OFF_QH 0
#define A_OFF_QL 18432
#define A_KV0 36864
#define A_KVSTAGE 36864
#define ATT_SMEM (A_KV0 + 3 * A_KVSTAGE)

__global__ void __launch_bounds__(256, 1)
attn_mma(const __nv_bfloat16* __restrict__ qkvh, const __nv_bfloat16* __restrict__ qkvl,
         __nv_bfloat16* __restrict__ Oh, __nv_bfloat16* __restrict__ Ol) {
    extern __shared__ char smem[];
    const uint32_t sb = smem_u32(smem);
    const int tid = threadIdx.x;
    const int warp = tid >> 5, lane = tid & 31;
    const int qt = 7 - blockIdx.x;
    const int b = blockIdx.y >> 4, h = blockIdx.y & 15;
    const int qrow0 = qt * 128;
    const size_t rowbase = (size_t)b * SS;
    const int jlast = 2 * qt + 1;

#pragma unroll
    for (int i = 0; i < 4; i++) {
        const int idx = tid + i * 256;
        const int row = idx >> 3;
        const int c8 = (idx & 7) * 8;
        const size_t g = (rowbase + qrow0 + row) * 3072 + h * DH + c8;
        const uint32_t so = sb + (uint32_t)row * RSTRIDE + (uint32_t)c8 * 2;
        CP_ASYNC16(so + A_OFF_QH, qkvh + g);
        CP_ASYNC16(so + A_OFF_QL, qkvl + g);
    }
    auto issue_kv = [&](int j) {
        const uint32_t so = sb + A_KV0 + (uint32_t)(j % 3) * A_KVSTAGE;
#pragma unroll
        for (int i = 0; i < 2; i++) {
            const int idx = tid + i * 256;
            const int row = idx >> 3;
            const int c8 = (idx & 7) * 8;
            const size_t g = (rowbase + j * 64 + row) * 3072 + h * DH + c8;
            const uint32_t soff = so + (uint32_t)row * RSTRIDE + (uint32_t)c8 * 2;
            CP_ASYNC16(soff,         qkvh + g + 1024);
            CP_ASYNC16(soff + 9216,  qkvl + g + 1024);
            CP_ASYNC16(soff + 18432, qkvh + g + 2048);
            CP_ASYNC16(soff + 27648, qkvl + g + 2048);
        }
    };
    issue_kv(0); CP_COMMIT();
    if (jlast >= 1) { issue_kv(1); CP_COMMIT(); }

    if (jlast >= 1) { CP_WAIT1(); } else { CP_WAIT0(); }
    __syncthreads();

    uint32_t qh[4][4], ql[4][4];
    {
        const uint32_t qbase = sb + (uint32_t)(warp * 16 + (lane & 15)) * RSTRIDE
                             + (uint32_t)(lane >> 4) * 16;
#pragma unroll
        for (int ks = 0; ks < 4; ks++) {
            LDSM_X4(qh[ks], qbase + A_OFF_QH + ks * 32);
            LDSM_X4(ql[ks], qbase + A_OFF_QL + ks * 32);
        }
    }

    float O[8][4];
#pragma unroll
    for (int dt = 0; dt < 8; dt++)
#pragma unroll
        for (int i = 0; i < 4; i++) O[dt][i] = 0.f;
    float m0 = -1e30f, m1 = -1e30f, l0 = 0.f, l1 = 0.f;

    const int rg0 = qrow0 + warp * 16 + (lane >> 2);
    const float SC = 0.18033688011112042f;

#pragma unroll 1
    for (int j = 0; j <= jlast; j++) {
        if (j + 2 <= jlast) { issue_kv(j + 2); CP_COMMIT(); }
        if (j + 2 <= jlast)      { CP_WAIT2(); }
        else if (j + 1 <= jlast) { CP_WAIT1(); }
        else                     { CP_WAIT0(); }
        __syncthreads();

        const bool active = (64 * j) <= (qrow0 + warp * 16 + 15);
        if (active) {
            const uint32_t so = sb + A_KV0 + (uint32_t)(j % 3) * A_KVSTAGE;

            float S[8][4];
#pragma unroll
            for (int nt = 0; nt < 8; nt++)
#pragma unroll
                for (int i = 0; i < 4; i++) S[nt][i] = 0.f;

            const uint32_t kbase = so + (uint32_t)(lane & 7) * RSTRIDE
                                 + (uint32_t)(lane >> 3) * 16;
#pragma unroll
            for (int nt = 0; nt < 8; nt++) {
                const uint32_t ka = kbase + nt * 8 * RSTRIDE;
                uint32_t kh0[4], kh1[4], kl0[4], kl1[4];
                LDSM_X4(kh0, ka);          LDSM_X4(kh1, ka + 64);
                LDSM_X4(kl0, ka + 9216);   LDSM_X4(kl1, ka + 9216 + 64);
                MMA16816V(S[nt], qh[0], kh0[0], kh0[1]);
                MMA16816V(S[nt], qh[1], kh0[2], kh0[3]);
                MMA16816V(S[nt], qh[2], kh1[0], kh1[1]);
                MMA16816V(S[nt], qh[3], kh1[2], kh1[3]);
                MMA16816V(S[nt], qh[0], kl0[0], kl0[1]);
                MMA16816V(S[nt], qh[1], kl0[2], kl0[3]);
                MMA16816V(S[nt], qh[2], kl1[0], kl1[1]);
                MMA16816V(S[nt], qh[3], kl1[2], kl1[3]);
                MMA16816V(S[nt], ql[0], kh0[0], kh0[1]);
                MMA16816V(S[nt], ql[1], kh0[2], kh0[3]);
                MMA16816V(S[nt], ql[2], kh1[0], kh1[1]);
                MMA16816V(S[nt], ql[3], kh1[2], kh1[3]);
            }

            const bool needmask = (j >= 2 * qt);
            float mx0 = -1e30f, mx1 = -1e30f;
#pragma unroll
            for (int nt = 0; nt < 8; nt++) {
                float t0 = S[nt][0] * SC, t1 = S[nt][1] * SC;
                float t2 = S[nt][2] * SC, t3 = S[nt][3] * SC;
                if (needmask) {
                    const int col = 64 * j + 8 * nt + 2 * (lane & 3);
                    if (col > rg0)         t0 = -1e30f;
                    if (col + 1 > rg0)     t1 = -1e30f;
                    if (col > rg0 + 8)     t2 = -1e30f;
                    if (col + 1 > rg0 + 8) t3 = -1e30f;
                }
                S[nt][0] = t0; S[nt][1] = t1; S[nt][2] = t2; S[nt][3] = t3;
                mx0 = fmaxf(mx0, fmaxf(t0, t1));
                mx1 = fmaxf(mx1, fmaxf(t2, t3));
            }
            mx0 = fmaxf(mx0, __shfl_xor_sync(0xffffffffu, mx0, 1));
            mx0 = fmaxf(mx0, __shfl_xor_sync(0xffffffffu, mx0, 2));
            mx1 = fmaxf(mx1, __shfl_xor_sync(0xffffffffu, mx1, 1));
            mx1 = fmaxf(mx1, __shfl_xor_sync(0xffffffffu, mx1, 2));

            const float mn0 = fmaxf(m0, mx0), mn1 = fmaxf(m1, mx1);
            const float cr0 = ex2(m0 - mn0), cr1 = ex2(m1 - mn1);
            m0 = mn0; m1 = mn1;

            float ls0 = 0.f, ls1 = 0.f;
#pragma unroll
            for (int nt = 0; nt < 8; nt++) {
                const float p0 = ex2(S[nt][0] - m0), p1 = ex2(S[nt][1] - m0);
                const float p2 = ex2(S[nt][2] - m1), p3 = ex2(S[nt][3] - m1);
                S[nt][0] = p0; S[nt][1] = p1; S[nt][2] = p2; S[nt][3] = p3;
                ls0 += p0 + p1;
                ls1 += p2 + p3;
            }
            ls0 += __shfl_xor_sync(0xffffffffu, ls0, 1);
            ls0 += __shfl_xor_sync(0xffffffffu, ls0, 2);
            ls1 += __shfl_xor_sync(0xffffffffu, ls1, 1);
            ls1 += __shfl_xor_sync(0xffffffffu, ls1, 2);
            l0 = l0 * cr0 + ls0;
            l1 = l1 * cr1 + ls1;

#pragma unroll
            for (int dt = 0; dt < 8; dt++) {
                O[dt][0] *= cr0; O[dt][1] *= cr0;
                O[dt][2] *= cr1; O[dt][3] *= cr1;
            }

            uint32_t ph[4][4], pl[4][4];
#pragma unroll
            for (int ks = 0; ks < 4; ks++) {
                split2(S[2 * ks][0],     S[2 * ks][1],     ph[ks][0], pl[ks][0]);
                split2(S[2 * ks][2],     S[2 * ks][3],     ph[ks][1], pl[ks][1]);
                split2(S[2 * ks + 1][0], S[2 * ks + 1][1], ph[ks][2], pl[ks][2]);
                split2(S[2 * ks + 1][2], S[2 * ks + 1][3], ph[ks][3], pl[ks][3]);
            }

            const uint32_t vbase = so + 18432 + (uint32_t)lane * RSTRIDE;
#pragma unroll
            for (int dt = 0; dt < 8; dt++) {
                const uint32_t va = vbase + dt * 16;
                uint32_t vh0[4], vh1[4], vl0[4], vl1[4];
                LDSM_X4_T(vh0, va);                 LDSM_X4_T(vh1, va + 32 * RSTRIDE);
                LDSM_X4_T(vl0, va + 9216);          LDSM_X4_T(vl1, va + 9216 + 32 * RSTRIDE);
                MMA16816V(O[dt], ph[0], vh0[0], vh0[1]);
                MMA16816V(O[dt], ph[1], vh0[2], vh0[3]);
                MMA16816V(O[dt], ph[2], vh1[0], vh1[1]);
                MMA16816V(O[dt], ph[3], vh1[2], vh1[3]);
                MMA16816V(O[dt], ph[0], vl0[0], vl0[1]);
                MMA16816V(O[dt], ph[1], vl0[2], vl0[3]);
                MMA16816V(O[dt], ph[2], vl1[0], vl1[1]);
                MMA16816V(O[dt], ph[3], vl1[2], vl1[3]);
                MMA16816V(O[dt], pl[0], vh0[0], vh0[1]);
                MMA16816V(O[dt], pl[1], vh0[2], vh0[3]);
                MMA16816V(O[dt], pl[2], vh1[0], vh1[1]);
                MMA16816V(O[dt], pl[3], vh1[2], vh1[3]);
            }
        }
        __syncthreads();
    }

    const float inv0 = 1.f / l0, inv1 = 1.f / l1;
    const size_t row0 = rowbase + qrow0 + warp * 16 + (lane >> 2);
    const size_t row1 = row0 + 8;
#pragma unroll
    for (int dt = 0; dt < 8; dt++) {
        const int col = h * DH + dt * 8 + 2 * (lane & 3);
        uint32_t h01, l01, h23, l23;
        split2(O[dt][0] * inv0, O[dt][1] * inv0, h01, l01);
        split2(O[dt][2] * inv1, O[dt][3] * inv1, h23, l23);
        *(uint32_t*)(Oh + row0 * DD + col) = h01;
        *(uint32_t*)(Ol + row0 * DD + col) = l01;
        *(uint32_t*)(Oh + row1 * DD + col) = h23;
        *(uint32_t*)(Ol + row1 * DD + col) = l23;
    }
}

// ---------------------------------------------------------------------------
extern "C" void kernel_launch(void* const* d_in, const int* in_sizes, int n_in,
                              void* d_out, int out_size) {
    const float* x     = (const float*)d_in[0];
    const float* w_qkv = (const float*)d_in[2];
    const float* w_out = (const float*)d_in[3];
    float* out = (float*)d_out;

    __nv_bfloat16 *wqh, *wql, *woh, *wol, *ah, *al, *qkvh, *qkvl;
    cudaGetSymbolAddress((void**)&wqh, g_wqkv_h);
    cudaGetSymbolAddress((void**)&wql, g_wqkv_l);
    cudaGetSymbolAddress((void**)&woh, g_wout_h);
    cudaGetSymbolAddress((void**)&wol, g_wout_l);
    cudaGetSymbolAddress((void**)&ah, g_ah);
    cudaGetSymbolAddress((void**)&al, g_al);
    cudaGetSymbolAddress((void**)&qkvh, g_qkvh);
    cudaGetSymbolAddress((void**)&qkvl, g_qkvl);

    cudaFuncSetAttribute((const void*)gemm_mma<192, true>,
                         cudaFuncAttributeMaxDynamicSharedMemorySize, GEMM_SMEM_192);
    cudaFuncSetAttribute((const void*)gemm_mma<256, false>,
                         cudaFuncAttributeMaxDynamicSharedMemorySize, GEMM_SMEM_256);
    cudaFuncSetAttribute(attn_mma, cudaFuncAttributeMaxDynamicSharedMemorySize, ATT_SMEM);

    // 0) weight transpose+split, activation split
    wsplit_kernel<<<dim3(3072 / 32, 1024 / 32), dim3(32, 8)>>>(w_qkv, wqh, wql, 1024, 3072);
    wsplit_kernel<<<dim3(1024 / 32, 1024 / 32), dim3(32, 8)>>>(w_out, woh, wol, 1024, 1024);
    xsplit_kernel<<<(8192 * 1024 / 4) / 256, 256>>>(x, ah, al);

    // 1) QKV projection: 128x192 tiles -> 1024 CTAs (~1% wave tail)
    gemm_mma<192, true><<<dim3(3072 / 192, 8192 / 128), 256, GEMM_SMEM_192>>>(
        ah, al, wqh, wql, nullptr, qkvh, qkvl, 3072);

    // 2) causal flash attention (HMMA) -> split bf16 O
    attn_mma<<<dim3(8, BB * HH), 256, ATT_SMEM>>>(qkvh, qkvl, ah, al);

    // 3) output projection: 128x256 tiles
    gemm_mma<256, false><<<dim3(1024 / 256, 8192 / 128), 256, GEMM_SMEM_256>>>(
        ah, al, woh, wol, out, nullptr, nullptr, 1024);
}